// round 10
// baseline (speedup 1.0000x reference)
#include <cuda_runtime.h>
#include <cuda_bf16.h>
#include <cstdint>
#include <cstddef>

#define NN 50000
#define NP 50048           // padded rows (multiple of 128)
#define EE 400000
#define DD 512
#define GG 128
#define LL 4
#define NSCAN_BLK 49       // ceil(50000/1024)

// ---------------- scratch (static device allocations; no cudaMalloc) -------
__device__ float g_h[(size_t)NN * DD];            // gemm2 output (pre-BN), fp32
__device__ __nv_bfloat16 g_ahi[(size_t)NP * DD];  // agg output, split hi
__device__ __nv_bfloat16 g_alo[(size_t)NP * DD];  // agg output, split lo
__device__ __nv_bfloat16 g_thi[(size_t)NP * DD];  // gemm1 output, split hi
__device__ __nv_bfloat16 g_tlo[(size_t)NP * DD];  // gemm1 output, split lo
__device__ __nv_bfloat16 g_whi[(size_t)8 * DD * DD];  // W^T split hi, [mat][n][k]
__device__ __nv_bfloat16 g_wlo[(size_t)8 * DD * DD];  // W^T split lo
__device__ int   g_deg[NN];
__device__ int   g_rowptr[NN + 1];
__device__ int   g_cursor[NN];
__device__ int   g_colidx[EE];
__device__ int   g_bsum[NSCAN_BLK];
__device__ int   g_gc[GG];
__device__ int   g_gstart[GG + 1];
__device__ float g_invcnt[GG];
__device__ float g_sum[DD];
__device__ float g_sq[DD];
__device__ float g_mu[DD];
__device__ float g_rstd[DD];

// ---------------- helpers ---------------------------------------------------
__device__ __forceinline__ void split2(float x, float y, uint32_t& hi, uint32_t& lo) {
    __nv_bfloat162 h = __floats2bfloat162_rn(x, y);   // .x in low 16 bits
    float hx = __bfloat162float(h.x);
    float hy = __bfloat162float(h.y);
    __nv_bfloat162 l = __floats2bfloat162_rn(x - hx, y - hy);
    hi = *(uint32_t*)&h;
    lo = *(uint32_t*)&l;
}

__device__ __forceinline__ void mma_bf16(float* c, const uint32_t* a, const uint32_t* b) {
    asm volatile(
        "mma.sync.aligned.m16n8k16.row.col.f32.bf16.bf16.f32 "
        "{%0,%1,%2,%3}, {%4,%5,%6,%7}, {%8,%9}, {%0,%1,%2,%3};\n"
        : "+f"(c[0]), "+f"(c[1]), "+f"(c[2]), "+f"(c[3])
        : "r"(a[0]), "r"(a[1]), "r"(a[2]), "r"(a[3]), "r"(b[0]), "r"(b[1]));
}

__device__ __forceinline__ void cp_async16(uint32_t saddr, const void* gaddr) {
    asm volatile("cp.async.cg.shared.global [%0], [%1], 16;\n"
                 :: "r"(saddr), "l"(gaddr));
}

#define LDSM4(r0, r1, r2, r3, a) \
    asm volatile("ldmatrix.sync.aligned.m8n8.x4.shared.b16 {%0,%1,%2,%3}, [%4];" \
                 : "=r"(r0), "=r"(r1), "=r"(r2), "=r"(r3) : "r"(a))

// ---------------- CSR build -------------------------------------------------
__global__ void zero_csr_kernel() {
    int i = blockIdx.x * blockDim.x + threadIdx.x;
    int stride = gridDim.x * blockDim.x;
    for (int j = i; j < NN; j += stride) g_deg[j] = 0;
    if (i < GG) g_gc[i] = 0;
    if (i < DD) { g_sum[i] = 0.f; g_sq[i] = 0.f; }
}

__global__ void edge_hist_kernel(const int* __restrict__ ei) {
    int e = blockIdx.x * blockDim.x + threadIdx.x;
    if (e < EE) atomicAdd(&g_deg[ei[EE + e]], 1);
}

__global__ void node_hist_kernel(const int* __restrict__ batch) {
    int i = blockIdx.x * blockDim.x + threadIdx.x;
    if (i < NN) atomicAdd(&g_gc[batch[i]], 1);
}

__global__ void scan1_kernel() {
    __shared__ int swarp[32];
    int tid = threadIdx.x;
    int i = blockIdx.x * 1024 + tid;
    int lane = tid & 31, w = tid >> 5;
    int v = (i < NN) ? g_deg[i] : 0;
    int x = v;
#pragma unroll
    for (int o = 1; o < 32; o <<= 1) {
        int y = __shfl_up_sync(0xffffffffu, x, o);
        if (lane >= o) x += y;
    }
    if (lane == 31) swarp[w] = x;
    __syncthreads();
    if (w == 0) {
        int s = swarp[lane];
#pragma unroll
        for (int o = 1; o < 32; o <<= 1) {
            int y = __shfl_up_sync(0xffffffffu, s, o);
            if (lane >= o) s += y;
        }
        swarp[lane] = s;
    }
    __syncthreads();
    int incl = x + (w > 0 ? swarp[w - 1] : 0);
    if (i < NN) g_rowptr[i + 1] = incl;
    if (tid == 1023) g_bsum[blockIdx.x] = incl;
}

__global__ void scan2_kernel() {
    if (threadIdx.x == 0) {
        int acc = 0;
        for (int b = 0; b < NSCAN_BLK; b++) {
            int v = g_bsum[b];
            g_bsum[b] = acc;
            acc += v;
        }
    }
}

__global__ void scan3_kernel() {
    int i = blockIdx.x * 1024 + threadIdx.x;
    if (i < NN) {
        int val = g_rowptr[i + 1] + g_bsum[blockIdx.x];
        g_rowptr[i + 1] = val;
        g_cursor[i] = val - g_deg[i];
        if (i == 0) g_rowptr[0] = 0;
    }
}

__global__ void scatter_kernel(const int* __restrict__ ei) {
    int e = blockIdx.x * blockDim.x + threadIdx.x;
    if (e < EE) {
        int d = ei[EE + e];
        int p = atomicAdd(&g_cursor[d], 1);
        g_colidx[p] = ei[e];
    }
}

__global__ void gscan_kernel() {
    if (threadIdx.x == 0) {
        int acc = 0;
        for (int g = 0; g < GG; g++) {
            g_gstart[g] = acc;
            int c = g_gc[g];
            acc += c;
            g_invcnt[g] = 1.0f / (float)(c > 1 ? c : 1);
        }
        g_gstart[GG] = acc;
    }
}

// ---------------- weight transpose + split: W[k][n] -> Wt[n][k] bf16 hi/lo --
__global__ void wsplit_kernel(const float* __restrict__ W1,
                              const float* __restrict__ W2) {
    __shared__ float tile[32][33];
    int mat = blockIdx.z;   // 0..7 : layer = mat>>1, (mat&1)? W2 : W1
    const float* W = ((mat & 1) ? W2 : W1) + (size_t)(mat >> 1) * DD * DD;
    int k0 = blockIdx.x * 32, n0 = blockIdx.y * 32;
    int tx = threadIdx.x, ty = threadIdx.y;
    tile[ty][tx] = W[(size_t)(k0 + ty) * DD + n0 + tx];
    __syncthreads();
    float v = tile[tx][ty];          // = W[k0+tx][n0+ty]
    __nv_bfloat16 h = __float2bfloat16_rn(v);
    __nv_bfloat16 l = __float2bfloat16_rn(v - __bfloat162float(h));
    size_t o = (size_t)mat * DD * DD + (size_t)(n0 + ty) * DD + k0 + tx;
    g_whi[o] = h;
    g_wlo[o] = l;
}

__global__ void padzero_kernel() {
    int i = blockIdx.x * 256 + threadIdx.x;
    if (i < (NP - NN) * DD) {
        size_t idx = (size_t)NN * DD + i;
        __nv_bfloat16 z = __float2bfloat16_rn(0.f);
        g_ahi[idx] = z; g_alo[idx] = z; g_thi[idx] = z; g_tlo[idx] = z;
    }
}

// ------- GIN aggregation with fused BN affine -------------------------------
__global__ void agg_kernel(const float* __restrict__ xin,
                           const float* __restrict__ gamma,
                           const float* __restrict__ beta) {
    const float* __restrict__ zin = xin ? xin : g_h;
    int n = blockIdx.x;
    int t = threadIdx.x;               // 128 threads, one float4 each
    const float4* Z = (const float4*)zin;
    float4 acc = Z[(size_t)n * 128 + t];
    int e = g_rowptr[n], end = g_rowptr[n + 1];
    int deg = end - e;
    for (; e + 4 <= end; e += 4) {
        int s0 = g_colidx[e], s1 = g_colidx[e + 1], s2 = g_colidx[e + 2], s3 = g_colidx[e + 3];
        float4 v0 = Z[(size_t)s0 * 128 + t];
        float4 v1 = Z[(size_t)s1 * 128 + t];
        float4 v2 = Z[(size_t)s2 * 128 + t];
        float4 v3 = Z[(size_t)s3 * 128 + t];
        acc.x += v0.x + v1.x + v2.x + v3.x;
        acc.y += v0.y + v1.y + v2.y + v3.y;
        acc.z += v0.z + v1.z + v2.z + v3.z;
        acc.w += v0.w + v1.w + v2.w + v3.w;
    }
    for (; e < end; e++) {
        float4 v = Z[(size_t)g_colidx[e] * 128 + t];
        acc.x += v.x; acc.y += v.y; acc.z += v.z; acc.w += v.w;
    }
    if (!xin) {
        int c = t * 4;
        float4 mu = *(const float4*)&g_mu[c];
        float4 rs = *(const float4*)&g_rstd[c];
        float4 ga = *(const float4*)&gamma[c];
        float4 be = *(const float4*)&beta[c];
        float k = (float)(deg + 1);
        float a0 = rs.x * ga.x, b0 = be.x - mu.x * a0;
        float a1 = rs.y * ga.y, b1 = be.y - mu.y * a1;
        float a2 = rs.z * ga.z, b2 = be.z - mu.z * a2;
        float a3 = rs.w * ga.w, b3 = be.w - mu.w * a3;
        acc.x = acc.x * a0 + b0 * k;
        acc.y = acc.y * a1 + b1 * k;
        acc.z = acc.z * a2 + b2 * k;
        acc.w = acc.w * a3 + b3 * k;
    }
    uint32_t h0, l0, h1, l1;
    split2(acc.x, acc.y, h0, l0);
    split2(acc.z, acc.w, h1, l1);
    ((uint2*)g_ahi)[(size_t)n * 128 + t] = make_uint2(h0, h1);
    ((uint2*)g_alo)[(size_t)n * 128 + t] = make_uint2(l0, l1);
}

// ------------- GEMM: C = relu(A @ W + bias), 3xBF16, ldmatrix + cp.async ----
#define SROW 20                // uint32 per row: 16 k-pairs + 4 pad
#define STAGE_U32 (4 * 128 * SROW)
#define GEMM_SMEM_BYTES (2 * STAGE_U32 * 4)

__global__ __launch_bounds__(256, 2) void gemm_bf16_kernel(
    int mode,            // 0: A=g_ahi/alo, out split -> g_thi/tlo ; 1: A=g_thi/tlo, out fp32 -> g_h (+stats)
    int woff,            // offset into g_whi/g_wlo (elements)
    const float* __restrict__ bias)
{
    extern __shared__ uint32_t smem[];
    __shared__ float ssum[128];
    __shared__ float ssq[128];
    const __nv_bfloat16* __restrict__ Ahi = mode ? g_thi : g_ahi;
    const __nv_bfloat16* __restrict__ Alo = mode ? g_tlo : g_alo;
    const __nv_bfloat16* __restrict__ Bhi = g_whi + woff;
    const __nv_bfloat16* __restrict__ Blo = g_wlo + woff;

    int tid  = threadIdx.x;
    int lane = tid & 31;
    int warp = tid >> 5;
    int wm = warp >> 1;          // 0..3
    int wn = warp & 1;           // 0..1
    int m0 = blockIdx.x * 128;
    int n0 = blockIdx.y * 128;

    if (tid < 128) { ssum[tid] = 0.f; ssq[tid] = 0.f; }

    float acc[2][8][4];
#pragma unroll
    for (int mi = 0; mi < 2; mi++)
#pragma unroll
        for (int ni = 0; ni < 8; ni++)
#pragma unroll
            for (int j = 0; j < 4; j++) acc[mi][ni][j] = 0.f;

    uint32_t sbase = (uint32_t)__cvta_generic_to_shared(smem);

    // ldmatrix per-lane address offsets (bytes, relative to sa/sb bases)
    int rsel = lane & 7, grp = lane >> 3;
    // A: tiles {rows+0,kp0},{rows+8,kp0},{rows+0,kp4},{rows+8,kp4}
    int a_row = (grp & 1) * 8 + rsel;
    int a_kp  = (grp >> 1) * 4;
    uint32_t aoff[2];
#pragma unroll
    for (int mi = 0; mi < 2; mi++)
        aoff[mi] = (uint32_t)(((wm * 32 + mi * 16 + a_row) * SROW + a_kp) * 4);
    // B: tiles {ni even,kp0},{ni even,kp4},{ni odd,kp0},{ni odd,kp4}
    int b_half = grp >> 1;           // 0: even ni, 1: odd ni of the pair
    int b_kp   = (grp & 1) * 4;
    uint32_t boff[4];
#pragma unroll
    for (int p = 0; p < 4; p++)
        boff[p] = (uint32_t)(((wn * 64 + (2 * p + b_half) * 8 + rsel) * SROW + b_kp) * 4);

    auto prefetch = [&](int kt, int s) {
        int k0 = kt * 32;
        uint32_t b = sbase + (uint32_t)s * STAGE_U32 * 4;
#pragma unroll
        for (int c = 0; c < 2; c++) {
            int id = tid + c * 256;          // 0..511
            int row = id >> 2;               // 0..127
            int cc = id & 3;                 // 16B chunk within row
            uint32_t doff = (uint32_t)(row * SROW + cc * 4) * 4u;
            size_t go = (size_t)row * DD + k0 + cc * 8;
            cp_async16(b + doff,                          Ahi + (size_t)m0 * DD + go);
            cp_async16(b + 128 * SROW * 4 + doff,         Alo + (size_t)m0 * DD + go);
            cp_async16(b + 2 * 128 * SROW * 4 + doff,     Bhi + (size_t)n0 * DD + go);
            cp_async16(b + 3 * 128 * SROW * 4 + doff,     Blo + (size_t)n0 * DD + go);
        }
        asm volatile("cp.async.commit_group;\n" ::);
    };

    prefetch(0, 0);

    for (int kt = 0; kt < 16; kt++) {
        if (kt < 15) {
            prefetch(kt + 1, (kt + 1) & 1);
            asm volatile("cp.async.wait_group 1;\n" ::);
        } else {
            asm volatile("cp.async.wait_group 0;\n" ::);
        }
        __syncthreads();

        uint32_t base  = sbase + (uint32_t)(kt & 1) * STAGE_U32 * 4;
        uint32_t aHiB = base;
        uint32_t aLoB = base + 128 * SROW * 4;
        uint32_t bHiB = base + 2 * 128 * SROW * 4;
        uint32_t bLoB = base + 3 * 128 * SROW * 4;

#pragma unroll
        for (int kk = 0; kk < 2; kk++) {
            uint32_t kb = (uint32_t)(kk * 8 * 4);
            uint32_t afh[2][4], afl[2][4], bfh[8][2], bfl[8][2];
#pragma unroll
            for (int mi = 0; mi < 2; mi++) {
                LDSM4(afh[mi][0], afh[mi][1], afh[mi][2], afh[mi][3], aHiB + aoff[mi] + kb);
                LDSM4(afl[mi][0], afl[mi][1], afl[mi][2], afl[mi][3], aLoB + aoff[mi] + kb);
            }
#pragma unroll
            for (int p = 0; p < 4; p++) {
                LDSM4(bfh[2 * p][0], bfh[2 * p][1], bfh[2 * p + 1][0], bfh[2 * p + 1][1],
                      bHiB + boff[p] + kb);
                LDSM4(bfl[2 * p][0], bfl[2 * p][1], bfl[2 * p + 1][0], bfl[2 * p + 1][1],
                      bLoB + boff[p] + kb);
            }
#pragma unroll
            for (int mi = 0; mi < 2; mi++)
#pragma unroll
                for (int ni = 0; ni < 8; ni++) {
                    mma_bf16(acc[mi][ni], afl[mi], bfh[ni]);   // a_lo * b_hi
                    mma_bf16(acc[mi][ni], afh[mi], bfl[ni]);   // a_hi * b_lo
                    mma_bf16(acc[mi][ni], afh[mi], bfh[ni]);   // a_hi * b_hi
                }
        }
        __syncthreads();
    }

    // epilogue: relu(acc + bias) (+ fused BN stats in mode 1)
    int rbase = m0 + wm * 32 + (lane >> 2);
    int cbase = n0 + wn * 64 + (lane & 3) * 2;
#pragma unroll
    for (int ni = 0; ni < 8; ni++) {
        int c = cbase + ni * 8;
        float b0 = __ldg(&bias[c]);
        float b1 = __ldg(&bias[c + 1]);
        float sx = 0.f, sy = 0.f, qx = 0.f, qy = 0.f;
#pragma unroll
        for (int mi = 0; mi < 2; mi++) {
#pragma unroll
            for (int half = 0; half < 2; half++) {
                int r = rbase + mi * 16 + half * 8;
                if (r < NN) {
                    float vx = fmaxf(acc[mi][ni][half * 2 + 0] + b0, 0.f);
                    float vy = fmaxf(acc[mi][ni][half * 2 + 1] + b1, 0.f);
                    if (mode == 0) {
                        uint32_t h, l;
                        split2(vx, vy, h, l);
                        *(uint32_t*)(g_thi + (size_t)r * DD + c) = h;
                        *(uint32_t*)(g_tlo + (size_t)r * DD + c) = l;
                    } else {
                        float2 v; v.x = vx; v.y = vy;
                        *(float2*)(g_h + (size_t)r * DD + c) = v;
                        sx += vx; sy += vy;
                        qx += vx * vx; qy += vy * vy;
                    }
                }
            }
        }
        if (mode == 1) {
            int crel = c - n0;
            atomicAdd(&ssum[crel], sx);
            atomicAdd(&ssum[crel + 1], sy);
            atomicAdd(&ssq[crel], qx);
            atomicAdd(&ssq[crel + 1], qy);
        }
    }
    if (mode == 1) {
        __syncthreads();
        if (tid < 128) {
            atomicAdd(&g_sum[n0 + tid], ssum[tid]);
            atomicAdd(&g_sq[n0 + tid], ssq[tid]);
        }
    }
}

// ---------------- BN finalize (self-zeroing) + pool -------------------------
__global__ void bn_finalize_kernel() {
    int c = threadIdx.x;
    if (c < DD) {
        float s = g_sum[c], q = g_sq[c];
        float mu  = s * (1.0f / NN);
        float var = q * (1.0f / NN) - mu * mu;
        g_mu[c]   = mu;
        g_rstd[c] = rsqrtf(fmaxf(var, 0.f) + 1e-5f);
        g_sum[c] = 0.f;           // ready for next layer's fused stats
        g_sq[c]  = 0.f;
    }
}

__global__ void bn_pool_kernel(float* __restrict__ out, int layer,
                               const float* __restrict__ gamma,
                               const float* __restrict__ beta)
{
    int g   = blockIdx.x;
    int col = blockIdx.y * 128 + threadIdx.x;
    int s = g_gstart[g], e = g_gstart[g + 1];
    float a = g_rstd[col] * __ldg(&gamma[col]);
    float b = __ldg(&beta[col]) - g_mu[col] * a;
    float acc = 0.f;
    for (int r = s; r < e; r++)
        acc += g_h[(size_t)r * DD + col];
    float res = (e > s) ? acc * a * g_invcnt[g] + b : 0.f;
    out[g * (LL * DD) + layer * DD + col] = res;
}

// ---------------- launcher --------------------------------------------------
extern "C" void kernel_launch(void* const* d_in, const int* in_sizes, int n_in,
                              void* d_out, int out_size)
{
    const float* x     = (const float*)d_in[0];
    const float* W1    = (const float*)d_in[1];
    const float* b1    = (const float*)d_in[2];
    const float* W2    = (const float*)d_in[3];
    const float* b2    = (const float*)d_in[4];
    const float* gamma = (const float*)d_in[5];
    const float* beta  = (const float*)d_in[6];
    const int*   ei    = (const int*)d_in[7];     // int32 (JAX x64 disabled)
    const int*   batch = (const int*)d_in[8];     // int32
    float* out = (float*)d_out;

    cudaFuncSetAttribute(gemm_bf16_kernel,
                         cudaFuncAttributeMaxDynamicSharedMemorySize,
                         GEMM_SMEM_BYTES);

    wsplit_kernel<<<dim3(16, 16, 8), dim3(32, 32)>>>(W1, W2);
    padzero_kernel<<<((NP - NN) * DD + 255) / 256, 256>>>();
    zero_csr_kernel<<<196, 256>>>();
    edge_hist_kernel<<<(EE + 255) / 256, 256>>>(ei);
    node_hist_kernel<<<(NN + 255) / 256, 256>>>(batch);
    scan1_kernel<<<NSCAN_BLK, 1024>>>();
    scan2_kernel<<<1, 32>>>();
    scan3_kernel<<<NSCAN_BLK, 1024>>>();
    scatter_kernel<<<(EE + 255) / 256, 256>>>(ei);
    gscan_kernel<<<1, 32>>>();

    dim3 ggrid(NP / 128, 4);
    for (int i = 0; i < LL; i++) {
        agg_kernel<<<NN, 128>>>(i == 0 ? x : nullptr, gamma, beta);
        gemm_bf16_kernel<<<ggrid, 256, GEMM_SMEM_BYTES>>>(
            0, (2 * i) * DD * DD, b1 + i * DD);
        gemm_bf16_kernel<<<ggrid, 256, GEMM_SMEM_BYTES>>>(
            1, (2 * i + 1) * DD * DD, b2 + i * DD);
        bn_finalize_kernel<<<1, 512>>>();
        bn_pool_kernel<<<dim3(GG, 4), 128>>>(out, i, gamma, beta);
    }
}

// round 15
// speedup vs baseline: 1.0356x; 1.0356x over previous
#include <cuda_runtime.h>
#include <cuda_bf16.h>
#include <cstdint>
#include <cstddef>

#define NN 50000
#define NP 50048           // padded rows (multiple of 128)
#define EE 400000
#define DD 512
#define GG 128
#define LL 4
#define NSCAN_BLK 49       // ceil(50000/1024)

// ---------------- scratch (static device allocations; no cudaMalloc) -------
__device__ float g_h[(size_t)NN * DD];            // gemm2 output (pre-BN), fp32
__device__ __nv_bfloat16 g_ahi[(size_t)NP * DD];  // agg output, split hi
__device__ __nv_bfloat16 g_alo[(size_t)NP * DD];  // agg output, split lo
__device__ __nv_bfloat16 g_thi[(size_t)NP * DD];  // gemm1 output, split hi
__device__ __nv_bfloat16 g_tlo[(size_t)NP * DD];  // gemm1 output, split lo
__device__ __nv_bfloat16 g_whi[(size_t)8 * DD * DD];  // W^T split hi, [mat][n][k]
__device__ __nv_bfloat16 g_wlo[(size_t)8 * DD * DD];  // W^T split lo
__device__ float g_pool[(size_t)GG * DD];         // per-graph raw-h column sums
__device__ int   g_deg[NN];
__device__ int   g_rowptr[NN + 1];
__device__ int   g_cursor[NN];
__device__ int   g_colidx[EE];
__device__ int   g_bsum[NSCAN_BLK];
__device__ int   g_gc[GG];
__device__ int   g_gstart[GG + 1];
__device__ float g_invcnt[GG];
__device__ float g_sum[DD];
__device__ float g_sq[DD];
__device__ float g_mu[DD];
__device__ float g_rstd[DD];

// ---------------- helpers ---------------------------------------------------
__device__ __forceinline__ void split2(float x, float y, uint32_t& hi, uint32_t& lo) {
    __nv_bfloat162 h = __floats2bfloat162_rn(x, y);   // .x in low 16 bits
    float hx = __bfloat162float(h.x);
    float hy = __bfloat162float(h.y);
    __nv_bfloat162 l = __floats2bfloat162_rn(x - hx, y - hy);
    hi = *(uint32_t*)&h;
    lo = *(uint32_t*)&l;
}

__device__ __forceinline__ void mma_bf16(float* c, const uint32_t* a, const uint32_t* b) {
    asm volatile(
        "mma.sync.aligned.m16n8k16.row.col.f32.bf16.bf16.f32 "
        "{%0,%1,%2,%3}, {%4,%5,%6,%7}, {%8,%9}, {%0,%1,%2,%3};\n"
        : "+f"(c[0]), "+f"(c[1]), "+f"(c[2]), "+f"(c[3])
        : "r"(a[0]), "r"(a[1]), "r"(a[2]), "r"(a[3]), "r"(b[0]), "r"(b[1]));
}

__device__ __forceinline__ void cp_async16(uint32_t saddr, const void* gaddr) {
    asm volatile("cp.async.cg.shared.global [%0], [%1], 16;\n"
                 :: "r"(saddr), "l"(gaddr));
}

// ---------------- CSR build -------------------------------------------------
__global__ void zero_csr_kernel() {
    int i = blockIdx.x * blockDim.x + threadIdx.x;
    int stride = gridDim.x * blockDim.x;
    for (int j = i; j < NN; j += stride) g_deg[j] = 0;
    for (int j = i; j < GG * DD; j += stride) g_pool[j] = 0.f;
    if (i < GG) g_gc[i] = 0;
    if (i < DD) { g_sum[i] = 0.f; g_sq[i] = 0.f; }
}

__global__ void edge_hist_kernel(const int* __restrict__ ei) {
    int e = blockIdx.x * blockDim.x + threadIdx.x;
    if (e < EE) atomicAdd(&g_deg[ei[EE + e]], 1);
}

__global__ void node_hist_kernel(const int* __restrict__ batch) {
    int i = blockIdx.x * blockDim.x + threadIdx.x;
    if (i < NN) atomicAdd(&g_gc[batch[i]], 1);
}

__global__ void scan1_kernel() {
    __shared__ int swarp[32];
    int tid = threadIdx.x;
    int i = blockIdx.x * 1024 + tid;
    int lane = tid & 31, w = tid >> 5;
    int v = (i < NN) ? g_deg[i] : 0;
    int x = v;
#pragma unroll
    for (int o = 1; o < 32; o <<= 1) {
        int y = __shfl_up_sync(0xffffffffu, x, o);
        if (lane >= o) x += y;
    }
    if (lane == 31) swarp[w] = x;
    __syncthreads();
    if (w == 0) {
        int s = swarp[lane];
#pragma unroll
        for (int o = 1; o < 32; o <<= 1) {
            int y = __shfl_up_sync(0xffffffffu, s, o);
            if (lane >= o) s += y;
        }
        swarp[lane] = s;
    }
    __syncthreads();
    int incl = x + (w > 0 ? swarp[w - 1] : 0);
    if (i < NN) g_rowptr[i + 1] = incl;
    if (tid == 1023) g_bsum[blockIdx.x] = incl;
}

__global__ void scan2_kernel() {
    if (threadIdx.x == 0) {
        int acc = 0;
        for (int b = 0; b < NSCAN_BLK; b++) {
            int v = g_bsum[b];
            g_bsum[b] = acc;
            acc += v;
        }
    }
}

__global__ void scan3_kernel() {
    int i = blockIdx.x * 1024 + threadIdx.x;
    if (i < NN) {
        int val = g_rowptr[i + 1] + g_bsum[blockIdx.x];
        g_rowptr[i + 1] = val;
        g_cursor[i] = val - g_deg[i];
        if (i == 0) g_rowptr[0] = 0;
    }
}

__global__ void scatter_kernel(const int* __restrict__ ei) {
    int e = blockIdx.x * blockDim.x + threadIdx.x;
    if (e < EE) {
        int d = ei[EE + e];
        int p = atomicAdd(&g_cursor[d], 1);
        g_colidx[p] = ei[e];
    }
}

__global__ void gscan_kernel() {
    if (threadIdx.x == 0) {
        int acc = 0;
        for (int g = 0; g < GG; g++) {
            g_gstart[g] = acc;
            int c = g_gc[g];
            acc += c;
            g_invcnt[g] = 1.0f / (float)(c > 1 ? c : 1);
        }
        g_gstart[GG] = acc;
    }
}

// ---------------- weight transpose + split: W[k][n] -> Wt[n][k] bf16 hi/lo --
__global__ void wsplit_kernel(const float* __restrict__ W1,
                              const float* __restrict__ W2) {
    __shared__ float tile[32][33];
    int mat = blockIdx.z;   // 0..7 : layer = mat>>1, (mat&1)? W2 : W1
    const float* W = ((mat & 1) ? W2 : W1) + (size_t)(mat >> 1) * DD * DD;
    int k0 = blockIdx.x * 32, n0 = blockIdx.y * 32;
    int tx = threadIdx.x, ty = threadIdx.y;
    tile[ty][tx] = W[(size_t)(k0 + ty) * DD + n0 + tx];
    __syncthreads();
    float v = tile[tx][ty];          // = W[k0+tx][n0+ty]
    __nv_bfloat16 h = __float2bfloat16_rn(v);
    __nv_bfloat16 l = __float2bfloat16_rn(v - __bfloat162float(h));
    size_t o = (size_t)mat * DD * DD + (size_t)(n0 + ty) * DD + k0 + tx;
    g_whi[o] = h;
    g_wlo[o] = l;
}

__global__ void padzero_kernel() {
    int i = blockIdx.x * 256 + threadIdx.x;
    if (i < (NP - NN) * DD) {
        size_t idx = (size_t)NN * DD + i;
        __nv_bfloat16 z = __float2bfloat16_rn(0.f);
        g_ahi[idx] = z; g_alo[idx] = z; g_thi[idx] = z; g_tlo[idx] = z;
    }
}

// ------- GIN aggregation with fused BN affine -------------------------------
__global__ void agg_kernel(const float* __restrict__ xin,
                           const float* __restrict__ gamma,
                           const float* __restrict__ beta) {
    const float* __restrict__ zin = xin ? xin : g_h;
    int n = blockIdx.x;
    int t = threadIdx.x;               // 128 threads, one float4 each
    const float4* Z = (const float4*)zin;
    float4 acc = Z[(size_t)n * 128 + t];
    int e = g_rowptr[n], end = g_rowptr[n + 1];
    int deg = end - e;
    for (; e + 4 <= end; e += 4) {
        int s0 = g_colidx[e], s1 = g_colidx[e + 1], s2 = g_colidx[e + 2], s3 = g_colidx[e + 3];
        float4 v0 = Z[(size_t)s0 * 128 + t];
        float4 v1 = Z[(size_t)s1 * 128 + t];
        float4 v2 = Z[(size_t)s2 * 128 + t];
        float4 v3 = Z[(size_t)s3 * 128 + t];
        acc.x += v0.x + v1.x + v2.x + v3.x;
        acc.y += v0.y + v1.y + v2.y + v3.y;
        acc.z += v0.z + v1.z + v2.z + v3.z;
        acc.w += v0.w + v1.w + v2.w + v3.w;
    }
    for (; e < end; e++) {
        float4 v = Z[(size_t)g_colidx[e] * 128 + t];
        acc.x += v.x; acc.y += v.y; acc.z += v.z; acc.w += v.w;
    }
    if (!xin) {
        int c = t * 4;
        float4 mu = *(const float4*)&g_mu[c];
        float4 rs = *(const float4*)&g_rstd[c];
        float4 ga = *(const float4*)&gamma[c];
        float4 be = *(const float4*)&beta[c];
        float k = (float)(deg + 1);
        float a0 = rs.x * ga.x, b0 = be.x - mu.x * a0;
        float a1 = rs.y * ga.y, b1 = be.y - mu.y * a1;
        float a2 = rs.z * ga.z, b2 = be.z - mu.z * a2;
        float a3 = rs.w * ga.w, b3 = be.w - mu.w * a3;
        acc.x = acc.x * a0 + b0 * k;
        acc.y = acc.y * a1 + b1 * k;
        acc.z = acc.z * a2 + b2 * k;
        acc.w = acc.w * a3 + b3 * k;
    }
    uint32_t h0, l0, h1, l1;
    split2(acc.x, acc.y, h0, l0);
    split2(acc.z, acc.w, h1, l1);
    ((uint2*)g_ahi)[(size_t)n * 128 + t] = make_uint2(h0, h1);
    ((uint2*)g_alo)[(size_t)n * 128 + t] = make_uint2(l0, l1);
}

// ------------- GEMM: C = relu(A @ W + bias), 3xBF16, cp.async pipeline ------
// mode 1 epilogue: writes fp32 g_h, accumulates BN stats (smem->global atomics)
// AND pools raw h into g_pool[batch[r]][c] via global atomics (coalesced when
// the thread's 4 rows share one graph, the ~94% case with sorted batch).
#define SROW 20                // uint32 per row: 16 k-pairs + 4 pad
#define STAGE_U32 (4 * 128 * SROW)
#define GEMM_SMEM_BYTES (2 * STAGE_U32 * 4)

__global__ __launch_bounds__(256, 2) void gemm_bf16_kernel(
    int mode,            // 0: A=g_ahi/alo, out split -> g_thi/tlo ; 1: A=g_thi/tlo, out fp32 -> g_h (+stats +pool)
    int woff,            // offset into g_whi/g_wlo (elements)
    const float* __restrict__ bias,
    const int* __restrict__ batch)
{
    extern __shared__ uint32_t smem[];
    __shared__ float ssum[128];
    __shared__ float ssq[128];
    const __nv_bfloat16* __restrict__ Ahi = mode ? g_thi : g_ahi;
    const __nv_bfloat16* __restrict__ Alo = mode ? g_tlo : g_alo;
    const __nv_bfloat16* __restrict__ Bhi = g_whi + woff;
    const __nv_bfloat16* __restrict__ Blo = g_wlo + woff;

    int tid  = threadIdx.x;
    int lane = tid & 31;
    int warp = tid >> 5;
    int wm = warp >> 1;          // 0..3
    int wn = warp & 1;           // 0..1
    int m0 = blockIdx.x * 128;
    int n0 = blockIdx.y * 128;

    if (tid < 128) { ssum[tid] = 0.f; ssq[tid] = 0.f; }

    float acc[2][8][4];
#pragma unroll
    for (int mi = 0; mi < 2; mi++)
#pragma unroll
        for (int ni = 0; ni < 8; ni++)
#pragma unroll
            for (int j = 0; j < 4; j++) acc[mi][ni][j] = 0.f;

    uint32_t sbase = (uint32_t)__cvta_generic_to_shared(smem);

    auto prefetch = [&](int kt, int s) {
        int k0 = kt * 32;
        uint32_t b = sbase + (uint32_t)s * STAGE_U32 * 4;
#pragma unroll
        for (int c = 0; c < 2; c++) {
            int id = tid + c * 256;          // 0..511
            int row = id >> 2;               // 0..127
            int cc = id & 3;                 // 16B chunk within row
            uint32_t doff = (uint32_t)(row * SROW + cc * 4) * 4u;
            size_t go = (size_t)row * DD + k0 + cc * 8;
            cp_async16(b + doff,                          Ahi + (size_t)m0 * DD + go);
            cp_async16(b + 128 * SROW * 4 + doff,         Alo + (size_t)m0 * DD + go);
            cp_async16(b + 2 * 128 * SROW * 4 + doff,     Bhi + (size_t)n0 * DD + go);
            cp_async16(b + 3 * 128 * SROW * 4 + doff,     Blo + (size_t)n0 * DD + go);
        }
        asm volatile("cp.async.commit_group;\n" ::);
    };

    prefetch(0, 0);

    for (int kt = 0; kt < 16; kt++) {
        if (kt < 15) {
            prefetch(kt + 1, (kt + 1) & 1);
            asm volatile("cp.async.wait_group 1;\n" ::);
        } else {
            asm volatile("cp.async.wait_group 0;\n" ::);
        }
        __syncthreads();

        uint32_t* buf   = smem + (kt & 1) * STAGE_U32;
        uint32_t* sa_hi = buf;
        uint32_t* sa_lo = buf + 128 * SROW;
        uint32_t* sb_hi = buf + 2 * 128 * SROW;
        uint32_t* sb_lo = buf + 3 * 128 * SROW;

#pragma unroll
        for (int kk = 0; kk < 2; kk++) {
            uint32_t afh[2][4], afl[2][4], bfh[8][2], bfl[8][2];
            int ar = wm * 32 + (lane >> 2);
            int ac = kk * 8 + (lane & 3);
#pragma unroll
            for (int mi = 0; mi < 2; mi++) {
                int r0 = ar + mi * 16;
                int i00 = r0 * SROW + ac;
                int i10 = (r0 + 8) * SROW + ac;
                afh[mi][0] = sa_hi[i00];     afh[mi][1] = sa_hi[i10];
                afh[mi][2] = sa_hi[i00 + 4]; afh[mi][3] = sa_hi[i10 + 4];
                afl[mi][0] = sa_lo[i00];     afl[mi][1] = sa_lo[i10];
                afl[mi][2] = sa_lo[i00 + 4]; afl[mi][3] = sa_lo[i10 + 4];
            }
            int bk = kk * 8 + (lane & 3);
            int bc = wn * 64 + (lane >> 2);
#pragma unroll
            for (int ni = 0; ni < 8; ni++) {
                int nidx = (bc + ni * 8) * SROW;
                bfh[ni][0] = sb_hi[nidx + bk]; bfh[ni][1] = sb_hi[nidx + bk + 4];
                bfl[ni][0] = sb_lo[nidx + bk]; bfl[ni][1] = sb_lo[nidx + bk + 4];
            }
#pragma unroll
            for (int mi = 0; mi < 2; mi++)
#pragma unroll
                for (int ni = 0; ni < 8; ni++) {
                    mma_bf16(acc[mi][ni], afl[mi], bfh[ni]);   // a_lo * b_hi
                    mma_bf16(acc[mi][ni], afh[mi], bfl[ni]);   // a_hi * b_lo
                    mma_bf16(acc[mi][ni], afh[mi], bfh[ni]);   // a_hi * b_hi
                }
        }
        __syncthreads();
    }

    // epilogue: relu(acc + bias) (+ fused BN stats and per-graph pool in mode 1)
    int rbase = m0 + wm * 32 + (lane >> 2);
    int cbase = n0 + wn * 64 + (lane & 3) * 2;
    int bg[2][2];
    bool same_g = false;
    if (mode == 1) {
#pragma unroll
        for (int mi = 0; mi < 2; mi++)
#pragma unroll
            for (int half = 0; half < 2; half++) {
                int r = rbase + mi * 16 + half * 8;
                bg[mi][half] = (r < NN) ? __ldg(&batch[r]) : -1;
            }
        same_g = (bg[0][0] == bg[0][1]) && (bg[0][0] == bg[1][0]) &&
                 (bg[0][0] == bg[1][1]) && (bg[0][0] >= 0);
    }
#pragma unroll
    for (int ni = 0; ni < 8; ni++) {
        int c = cbase + ni * 8;
        float b0 = __ldg(&bias[c]);
        float b1 = __ldg(&bias[c + 1]);
        float sx = 0.f, sy = 0.f, qx = 0.f, qy = 0.f;
#pragma unroll
        for (int mi = 0; mi < 2; mi++) {
#pragma unroll
            for (int half = 0; half < 2; half++) {
                int r = rbase + mi * 16 + half * 8;
                if (r < NN) {
                    float vx = fmaxf(acc[mi][ni][half * 2 + 0] + b0, 0.f);
                    float vy = fmaxf(acc[mi][ni][half * 2 + 1] + b1, 0.f);
                    if (mode == 0) {
                        uint32_t h, l;
                        split2(vx, vy, h, l);
                        *(uint32_t*)(g_thi + (size_t)r * DD + c) = h;
                        *(uint32_t*)(g_tlo + (size_t)r * DD + c) = l;
                    } else {
                        float2 v; v.x = vx; v.y = vy;
                        *(float2*)(g_h + (size_t)r * DD + c) = v;
                        sx += vx; sy += vy;
                        qx += vx * vx; qy += vy * vy;
                        if (!same_g) {
                            float* gp = g_pool + (size_t)bg[mi][half] * DD + c;
                            atomicAdd(gp, vx);
                            atomicAdd(gp + 1, vy);
                        }
                    }
                }
            }
        }
        if (mode == 1) {
            if (same_g) {
                // all 4 rows in one graph: single atomic pair of the local sums
                float* gp = g_pool + (size_t)bg[0][0] * DD + c;
                atomicAdd(gp, sx);
                atomicAdd(gp + 1, sy);
            }
            int crel = c - n0;
            atomicAdd(&ssum[crel], sx);
            atomicAdd(&ssum[crel + 1], sy);
            atomicAdd(&ssq[crel], qx);
            atomicAdd(&ssq[crel + 1], qy);
        }
    }
    if (mode == 1) {
        __syncthreads();
        if (tid < 128) {
            atomicAdd(&g_sum[n0 + tid], ssum[tid]);
            atomicAdd(&g_sq[n0 + tid], ssq[tid]);
        }
    }
}

// ---------------- BN finalize (self-zeroing) --------------------------------
__global__ void bn_finalize_kernel() {
    int c = threadIdx.x;
    if (c < DD) {
        float s = g_sum[c], q = g_sq[c];
        float mu  = s * (1.0f / NN);
        float var = q * (1.0f / NN) - mu * mu;
        g_mu[c]   = mu;
        g_rstd[c] = rsqrtf(fmaxf(var, 0.f) + 1e-5f);
        g_sum[c] = 0.f;           // ready for next layer's fused stats
        g_sq[c]  = 0.f;
    }
}

// write pooled output: (sum·a)·inv + b, then self-zero g_pool for next layer
__global__ void pool_write_kernel(float* __restrict__ out, int layer,
                                  const float* __restrict__ gamma,
                                  const float* __restrict__ beta)
{
    int g = blockIdx.x;
    int c = threadIdx.x;     // 512
    float a = g_rstd[c] * __ldg(&gamma[c]);
    float b = __ldg(&beta[c]) - g_mu[c] * a;
    float s = g_pool[(size_t)g * DD + c];
    int cnt = g_gstart[g + 1] - g_gstart[g];
    out[g * (LL * DD) + layer * DD + c] = (cnt > 0) ? s * a * g_invcnt[g] + b : 0.f;
    g_pool[(size_t)g * DD + c] = 0.f;
}

// ---------------- launcher --------------------------------------------------
extern "C" void kernel_launch(void* const* d_in, const int* in_sizes, int n_in,
                              void* d_out, int out_size)
{
    const float* x     = (const float*)d_in[0];
    const float* W1    = (const float*)d_in[1];
    const float* b1    = (const float*)d_in[2];
    const float* W2    = (const float*)d_in[3];
    const float* b2    = (const float*)d_in[4];
    const float* gamma = (const float*)d_in[5];
    const float* beta  = (const float*)d_in[6];
    const int*   ei    = (const int*)d_in[7];     // int32 (JAX x64 disabled)
    const int*   batch = (const int*)d_in[8];     // int32
    float* out = (float*)d_out;

    cudaFuncSetAttribute(gemm_bf16_kernel,
                         cudaFuncAttributeMaxDynamicSharedMemorySize,
                         GEMM_SMEM_BYTES);

    wsplit_kernel<<<dim3(16, 16, 8), dim3(32, 32)>>>(W1, W2);
    padzero_kernel<<<((NP - NN) * DD + 255) / 256, 256>>>();
    zero_csr_kernel<<<196, 256>>>();
    edge_hist_kernel<<<(EE + 255) / 256, 256>>>(ei);
    node_hist_kernel<<<(NN + 255) / 256, 256>>>(batch);
    scan1_kernel<<<NSCAN_BLK, 1024>>>();
    scan2_kernel<<<1, 32>>>();
    scan3_kernel<<<NSCAN_BLK, 1024>>>();
    scatter_kernel<<<(EE + 255) / 256, 256>>>(ei);
    gscan_kernel<<<1, 32>>>();

    dim3 ggrid(NP / 128, 4);
    for (int i = 0; i < LL; i++) {
        agg_kernel<<<NN, 128>>>(i == 0 ? x : nullptr, gamma, beta);
        gemm_bf16_kernel<<<ggrid, 256, GEMM_SMEM_BYTES>>>(
            0, (2 * i) * DD * DD, b1 + i * DD, batch);
        gemm_bf16_kernel<<<ggrid, 256, GEMM_SMEM_BYTES>>>(
            1, (2 * i + 1) * DD * DD, b2 + i * DD, batch);
        bn_finalize_kernel<<<1, 512>>>();
        pool_write_kernel<<<GG, 512>>>(out, i, gamma, beta);
    }
}